// round 16
// baseline (speedup 1.0000x reference)
#include <cuda_runtime.h>

#define NT 8192
#define ND 2048
#define NE 16
#define CAP 512
#define FULLM 0xFFFFFFFFu
#define CINF 0x7FFFFFFF

typedef unsigned long long u64;

__device__ float g_probsT[NE * NT];             // softmax probs, transposed [e][t]
__device__ u64   g_prefs[NT];                   // packed preference order (16 nibbles)
__device__ unsigned g_ch[NT / 4];               // final choices (bytes)
__device__ int      g_bpre[NE * 32];            // global out-base per (expert, block)

__device__ __forceinline__ u64 ffma2(u64 a, u64 b, u64 c) {
    u64 d;
    asm("fma.rn.f32x2 %0, %1, %2, %3;" : "=l"(d) : "l"(a), "l"(b), "l"(c));
    return d;
}
__device__ __forceinline__ u64 addx2(u64 a, u64 b) {
    u64 d;
    asm("add.rn.f32x2 %0, %1, %2;" : "=l"(d) : "l"(a), "l"(b));
    return d;
}
__device__ __forceinline__ u64 splat2(float x) {
    u64 r;
    asm("mov.b64 %0, {%1, %1};" : "=l"(r) : "f"(x));
    return r;
}
__device__ __forceinline__ u64 shfl64_xor(u64 v, int m) {
    unsigned lo = (unsigned)v, hi = (unsigned)(v >> 32);
    lo = __shfl_xor_sync(FULLM, lo, m);
    hi = __shfl_xor_sync(FULLM, hi, m);
    return (u64)lo | ((u64)hi << 32);
}
__device__ __forceinline__ float4 ldcs4(const float4* p) {
    float4 v;
    asm("ld.global.cs.v4.f32 {%0,%1,%2,%3}, [%4];"
        : "=f"(v.x), "=f"(v.y), "=f"(v.z), "=f"(v.w) : "l"(p));
    return v;
}

// =====================================================================
// Kernel 1: GEMV with in-block W swizzle (wprep kernel deleted).
// smem: [0,128K) swizzled Wt (ulonglong2[8192]); [128K,160K) raw staging.
// =====================================================================
#define GEMV_SMEM (131072 + 32768)

__global__ void __launch_bounds__(256) gemv_kernel(const float* __restrict__ f,
                                                   const float* __restrict__ W,
                                                   const float* __restrict__ b) {
    extern __shared__ unsigned char smem[];
    ulonglong2* s_wt  = (ulonglong2*)smem;              // 8192 entries
    float*      s_raw = (float*)(smem + 131072);        // 16 x 512 floats

    const int tid  = threadIdx.x;
    const int lane = tid & 31;
    const int wid  = tid >> 5;
    const int t0   = (blockIdx.x * 8 + wid) * 8;

    // ---- prelude: build swizzled W in smem (4 chunks of 512 k's) ----
    const float4* Wf4 = (const float4*)W;
    for (int c = 0; c < 4; ++c) {
        if (c) __syncthreads();                          // s_raw reuse guard
        for (int m = tid; m < 2048; m += 256) {
            const int e = m >> 7, k4l = m & 127;
            ((float4*)s_raw)[m] = Wf4[e * 512 + c * 128 + k4l];
        }
        __syncthreads();
#pragma unroll
        for (int q = 0; q < 8; ++q) {
            const int d  = c * 2048 + q * 256 + tid;
            const int ln = d & 31, j = (d >> 5) & 3, kk = (d >> 7) & 3, i = d >> 9;
            const int kl = (i - c * 4) * 128 + ln * 4 + kk;
            const float w0 = s_raw[(4 * j + 0) * 512 + kl];
            const float w1 = s_raw[(4 * j + 1) * 512 + kl];
            const float w2 = s_raw[(4 * j + 2) * 512 + kl];
            const float w3 = s_raw[(4 * j + 3) * 512 + kl];
            ulonglong2 v;
            v.x = (u64)__float_as_uint(w0) | ((u64)__float_as_uint(w1) << 32);
            v.y = (u64)__float_as_uint(w2) | ((u64)__float_as_uint(w3) << 32);
            s_wt[d] = v;
        }
    }
    __syncthreads();

    const float4* F = reinterpret_cast<const float4*>(f + (size_t)t0 * ND);

    u64 acc[8][8];
#pragma unroll
    for (int t = 0; t < 8; ++t)
#pragma unroll
        for (int p = 0; p < 8; ++p) acc[t][p] = 0ull;

    for (int i = 0; i < 16; ++i) {
        const int k4 = i * 32 + lane;
        float4 a[8];
#pragma unroll
        for (int t = 0; t < 8; ++t) a[t] = ldcs4(F + t * 512 + k4);
#pragma unroll
        for (int kk = 0; kk < 4; ++kk) {
            const int base = ((i * 4 + kk) * 4) * 32 + lane;
            const ulonglong2 wA = s_wt[base];
            const ulonglong2 wB = s_wt[base + 32];
            const ulonglong2 wC = s_wt[base + 64];
            const ulonglong2 wD = s_wt[base + 96];
#pragma unroll
            for (int t = 0; t < 8; ++t) {
                const float av = kk == 0 ? a[t].x : kk == 1 ? a[t].y
                               : kk == 2 ? a[t].z : a[t].w;
                const u64 s = splat2(av);
                acc[t][0] = ffma2(s, wA.x, acc[t][0]);
                acc[t][1] = ffma2(s, wA.y, acc[t][1]);
                acc[t][2] = ffma2(s, wB.x, acc[t][2]);
                acc[t][3] = ffma2(s, wB.y, acc[t][3]);
                acc[t][4] = ffma2(s, wC.x, acc[t][4]);
                acc[t][5] = ffma2(s, wC.y, acc[t][5]);
                acc[t][6] = ffma2(s, wD.x, acc[t][6]);
                acc[t][7] = ffma2(s, wD.y, acc[t][7]);
            }
        }
    }

    u64 keep0 = 0, keep1 = 0;
#pragma unroll
    for (int t = 0; t < 8; ++t) {
#pragma unroll
        for (int p = 0; p < 8; ++p) {
            u64 v = acc[t][p];
#pragma unroll
            for (int o = 16; o; o >>= 1) v = addx2(v, shfl64_xor(v, o));
            if (lane == ((t & 3) * 8 + p)) { if (t < 4) keep0 = v; else keep1 = v; }
        }
    }

    const int p = lane & 7;
    const int g = lane >> 3;
    const float b0 = __ldg(b + 2 * p), b1 = __ldg(b + 2 * p + 1);

#pragma unroll
    for (int pass = 0; pass < 2; ++pass) {
        const int t = t0 + pass * 4 + g;
        const u64 P = pass ? keep1 : keep0;
        const float f0 = __uint_as_float((unsigned)P) + b0;
        const float f1 = __uint_as_float((unsigned)(P >> 32)) + b1;

        float m = fmaxf(f0, f1);
#pragma unroll
        for (int o = 1; o < 8; o <<= 1) m = fmaxf(m, __shfl_xor_sync(FULLM, m, o));
        const float e0 = __expf(f0 - m), e1 = __expf(f1 - m);
        float s = e0 + e1;
#pragma unroll
        for (int o = 1; o < 8; o <<= 1) s += __shfl_xor_sync(FULLM, s, o);
        const float inv = __fdividef(1.f, s);
        g_probsT[(2 * p) * NT + t]     = e0 * inv;
        g_probsT[(2 * p + 1) * NT + t] = e1 * inv;

        unsigned u0 = __float_as_uint(f0), u1 = __float_as_uint(f1);
        u0 = (u0 & 0x80000000u) ? ~u0 : (u0 | 0x80000000u);
        u1 = (u1 & 0x80000000u) ? ~u1 : (u1 | 0x80000000u);
        const u64 k0 = ((u64)u0 << 4) | (u64)(15 - 2 * p);
        const u64 k1 = ((u64)u1 << 4) | (u64)(14 - 2 * p);
        int r0 = (k1 > k0), r1 = (k0 > k1);
#pragma unroll
        for (int j = 1; j < 8; ++j) {
            const u64 o0 = shfl64_xor(k0, j);
            const u64 o1 = shfl64_xor(k1, j);
            r0 += (o0 > k0) + (o1 > k0);
            r1 += (o0 > k1) + (o1 > k1);
        }
        u64 n = ((u64)(2 * p) << (4 * r0)) | ((u64)(2 * p + 1) << (4 * r1));
#pragma unroll
        for (int o = 1; o < 8; o <<= 1) n |= shfl64_xor(n, o);
        if (p == 0) g_prefs[t] = n;
    }
}

// =====================================================================
// Kernel 2: phased balanced assignment (R14 version — best known).
// =====================================================================
#define S_PREF_OFF 0
#define S_CH_OFF   65536
#define S_BLK_OFF  73728                 // [16][32] int
#define S_INT_OFF  (73728 + 2048)
#define SMEM_BYTES (73728 + 2048 + 128)
// s_int: [16] active, [17] start, [18] cut A, [19] cut B

__global__ void __launch_bounds__(1024) assign_kernel() {
    if (blockIdx.x != 0) return;          // grid padded to defeat 1-CTA throttle
    extern __shared__ unsigned char smem[];
    u64*      s_pref = (u64*)(smem + S_PREF_OFF);
    unsigned* s_ch   = (unsigned*)(smem + S_CH_OFF);   // 2048 words
    int*      s_blk  = (int*)(smem + S_BLK_OFF);
    int*      s_int  = (int*)(smem + S_INT_OFF);

    const int tid  = threadIdx.x;
    const int lane = tid & 31;
    const int wid  = tid >> 5;

    for (int i = tid; i < NT; i += 1024) s_pref[i] = g_prefs[i];
    if (tid == 0) { s_int[16] = 0xFFFF; s_int[17] = 0; s_int[18] = CINF; s_int[19] = CINF; }
    __syncthreads();

    // ---- build: warp wid counts+writes its 256-token block ----
    {
        u64 c0 = 0, c1 = 0, c2 = 0, c3 = 0;
#pragma unroll
        for (int i = 0; i < 2; ++i) {
            const int w = wid * 64 + i * 32 + lane;
            unsigned word = 0;
#pragma unroll
            for (int bb = 0; bb < 4; ++bb) {
                const int c = (int)(s_pref[w * 4 + bb] & 15);
                word |= (unsigned)c << (bb * 8);
                const u64 inc = 1ull << ((c & 3) << 4);
                if      ((c >> 2) == 0) c0 += inc;
                else if ((c >> 2) == 1) c1 += inc;
                else if ((c >> 2) == 2) c2 += inc;
                else                    c3 += inc;
            }
            s_ch[w] = word;
        }
#pragma unroll
        for (int o = 16; o; o >>= 1) {
            c0 += __shfl_xor_sync(FULLM, c0, o);
            c1 += __shfl_xor_sync(FULLM, c1, o);
            c2 += __shfl_xor_sync(FULLM, c2, o);
            c3 += __shfl_xor_sync(FULLM, c3, o);
        }
        if (lane < NE) {
            const u64 sel = (lane >> 2) == 0 ? c0 : (lane >> 2) == 1 ? c1
                          : (lane >> 2) == 2 ? c2 : c3;
            s_blk[lane * 32 + wid] = (int)((sel >> ((lane & 3) << 4)) & 0xFFFF);
        }
    }
    __syncthreads();

    // ---------------- phase loop ----------------
    for (int phase = 0; phase < NE; ++phase) {
        const int s = s_int[17];
        const int active  = s_int[16];
        const int cutslot = 18 + (phase & 1);

        if (wid < NE && ((active >> wid) & 1)) {
            const int e = wid;
            const unsigned splat = (unsigned)e * 0x01010101u;
            const int pb   = s >> 8;
            const int ws   = s >> 2;
            const int we_  = (pb + 1) * 64;
            const unsigned mfirst = 0xFFFFFFFFu << ((s & 3) * 8);

            const int i0 = ws + lane * 2;
            unsigned cm0 = 0, cm1 = 0;
            if (i0 < we_) {
                cm0 = __vcmpeq4(s_ch[i0], splat);
                if (i0 == ws) cm0 &= mfirst;
            }
            if (i0 + 1 < we_) cm1 = __vcmpeq4(s_ch[i0 + 1], splat);
            const int lcnt = (__popc(cm0) + __popc(cm1)) >> 3;
            const int ptotal = (int)__reduce_add_sync(FULLM, (unsigned)lcnt);

            const int bfull = s_blk[e * 32 + lane];
            int incl = bfull;
#pragma unroll
            for (int o = 1; o < 32; o <<= 1) {
                const int u = __shfl_up_sync(FULLM, incl, o);
                if (lane >= o) incl += u;
            }
            const int tot     = __shfl_sync(FULLM, incl, 31);
            const int pref_pb = __shfl_sync(FULLM, incl, pb);
            const int need    = CAP - (pref_pb - ptotal);
            const int live    = tot - pref_pb + ptotal;

            if (live >= need) {
                if (ptotal >= need) {
                    int linc = lcnt;
#pragma unroll
                    for (int o = 1; o < 32; o <<= 1) {
                        const int u = __shfl_up_sync(FULLM, linc, o);
                        if (lane >= o) linc += u;
                    }
                    const unsigned bal = __ballot_sync(FULLM, linc >= need);
                    const int cl = __ffs(bal) - 1;
                    if (lane == cl) {
                        int rem = need - (linc - lcnt);
                        int pos = -1;
#pragma unroll
                        for (int bb = 0; bb < 4 && pos < 0; ++bb)
                            if ((cm0 >> (bb * 8)) & 1u && --rem == 0) pos = i0 * 4 + bb;
#pragma unroll
                        for (int bb = 0; bb < 4 && pos < 0; ++bb)
                            if ((cm1 >> (bb * 8)) & 1u && --rem == 0) pos = (i0 + 1) * 4 + bb;
                        atomicMin(&s_int[cutslot], (pos << 4) | e);
                    }
                } else {
                    const int rem2 = need - ptotal;
                    const int minc = incl - pref_pb;
                    const unsigned bal = __ballot_sync(FULLM, lane > pb && minc >= rem2);
                    const int kc   = __ffs(bal) - 1;
                    const int excl = __shfl_sync(FULLM, incl - bfull, kc) - pref_pb;
                    const int rem3 = rem2 - excl;
                    const int j0 = kc * 64 + lane * 2;
                    const unsigned d0 = __vcmpeq4(s_ch[j0], splat);
                    const unsigned d1 = __vcmpeq4(s_ch[j0 + 1], splat);
                    const int lc = (__popc(d0) + __popc(d1)) >> 3;
                    int li = lc;
#pragma unroll
                    for (int o = 1; o < 32; o <<= 1) {
                        const int u = __shfl_up_sync(FULLM, li, o);
                        if (lane >= o) li += u;
                    }
                    const unsigned bal2 = __ballot_sync(FULLM, li >= rem3);
                    const int cl2 = __ffs(bal2) - 1;
                    if (lane == cl2) {
                        int rem = rem3 - (li - lc);
                        int pos = -1;
#pragma unroll
                        for (int bb = 0; bb < 4 && pos < 0; ++bb)
                            if ((d0 >> (bb * 8)) & 1u && --rem == 0) pos = j0 * 4 + bb;
#pragma unroll
                        for (int bb = 0; bb < 4 && pos < 0; ++bb)
                            if ((d1 >> (bb * 8)) & 1u && --rem == 0) pos = (j0 + 1) * 4 + bb;
                        atomicMin(&s_int[cutslot], (pos << 4) | e);
                    }
                }
            }
        }
        __syncthreads();                               // B1: cut final

        const int mv = s_int[cutslot];
        if (mv == CINF) {
            if (tid == 0) s_int[17] = NT;
            __syncthreads();
            continue;
        }
        const int pstar = mv >> 4, es = mv & 15;
        const int nactive = active & ~(1 << es);

        if (tid == 0) {
            s_int[16] = nactive;
            s_int[17] = pstar + 1;
            s_int[cutslot] = CINF;
        }
        {
            const int sn = pstar + 1;
            const int ws = sn >> 2;
            const unsigned splat = (unsigned)es * 0x01010101u;
            const unsigned mfirst = 0xFFFFFFFFu << ((sn & 3) * 8);
            for (int w = ws + tid; w < 2048; w += 1024) {
                unsigned word = s_ch[w];
                unsigned m = __vcmpeq4(word, splat);
                if (w == ws) m &= mfirst;
                if (m) {
                    const int blk = w >> 6;
                    int moved = 0;
                    do {
                        const int bb = (__ffs(m) - 1) >> 3;
                        m &= ~(0xFFu << (bb * 8));
                        u64 pw = s_pref[w * 4 + bb];
                        int c = (int)(pw & 15);
                        while (!((nactive >> c) & 1)) { pw >>= 4; c = (int)(pw & 15); }
                        word = (word & ~(0xFFu << (bb * 8))) | ((unsigned)c << (bb * 8));
                        atomicAdd(&s_blk[c * 32 + blk], 1);
                        ++moved;
                    } while (m);
                    atomicAdd(&s_blk[es * 32 + blk], -moved);
                    s_ch[w] = word;
                }
            }
        }
        __syncthreads();                               // B2: phase done
    }

    // ---- dump choices + per-(expert, block) OUTPUT BASES (prefixed) ----
    for (int i = tid; i < NT / 4; i += 1024) g_ch[i] = s_ch[i];
    if (wid < NE) {
        const int v = s_blk[wid * 32 + lane];
        int incl = v;
#pragma unroll
        for (int o = 1; o < 32; o <<= 1) {
            const int u = __shfl_up_sync(FULLM, incl, o);
            if (lane >= o) incl += u;
        }
        g_bpre[wid * 32 + lane] = wid * CAP + incl - v;   // exclusive prefix
    }
}

// =====================================================================
// Kernel 3: wide epilogue (R14 version)
// =====================================================================
__global__ void __launch_bounds__(256) epilogue_kernel(float* __restrict__ out) {
    __shared__ int s_base[NE];
    __shared__ int s_cnt[8][NE];
    const int b = blockIdx.x, tid = threadIdx.x;
    const int lane = tid & 31, wid = tid >> 5;
    const unsigned ltm = (1u << lane) - 1u;

    if (tid < NE) s_base[tid] = g_bpre[tid * 32 + b];
    if (tid < 8 * NE) s_cnt[tid >> 4][tid & 15] = 0;
    __syncthreads();

    const int t = b * 256 + tid;
    const int e = (int)((g_ch[t >> 2] >> ((t & 3) * 8)) & 0xFFu);
    const unsigned mask = __match_any_sync(FULLM, e);
    const int leader = __ffs(mask) - 1;
    if (lane == leader) s_cnt[wid][e] = __popc(mask);
    __syncthreads();

    if (tid < NE) {
        int acc = 0;
#pragma unroll
        for (int w = 0; w < 8; ++w) {
            const int v = s_cnt[w][tid];
            s_cnt[w][tid] = acc;
            acc += v;
        }
    }
    __syncthreads();

    const int rank = s_base[e] + s_cnt[wid][e] + __popc(mask & ltm);
    out[rank] = (float)t;
    out[NT + t] = g_probsT[e * NT + t];
}

// =====================================================================
extern "C" void kernel_launch(void* const* d_in, const int* in_sizes, int n_in,
                              void* d_out, int out_size) {
    const float* f = (const float*)d_in[0];   // features [8192, 2048] f32
    const float* W = (const float*)d_in[1];   // gate weight [16, 2048] f32
    const float* b = (const float*)d_in[2];   // bias [16] f32
    float* out = (float*)d_out;               // [8192] sort_by_expert ++ [8192] gathered

    cudaFuncSetAttribute(gemv_kernel,
                         cudaFuncAttributeMaxDynamicSharedMemorySize, GEMV_SMEM);
    gemv_kernel<<<NT / 64, 256, GEMV_SMEM>>>(f, W, b);

    cudaFuncSetAttribute(assign_kernel,
                         cudaFuncAttributeMaxDynamicSharedMemorySize, SMEM_BYTES);
    assign_kernel<<<148, 1024, SMEM_BYTES>>>();

    epilogue_kernel<<<NT / 256, 256>>>(out);
}

// round 17
// speedup vs baseline: 1.0835x; 1.0835x over previous
#include <cuda_runtime.h>

#define NT 8192
#define ND 2048
#define NE 16
#define CAP 512
#define FULLM 0xFFFFFFFFu
#define CINF 0x7FFFFFFF

typedef unsigned long long u64;

__device__ float g_probsT[NE * NT];             // softmax probs, transposed [e][t]
__device__ u64   g_prefs[NT];                   // packed preference order (16 nibbles)
__device__ __align__(16) u64 g_Wt[ND * NE / 2]; // swizzled W, expert-pair packed
__device__ unsigned g_ch[NT / 4];               // final choices (bytes)
__device__ int      g_bpre[NE * 32];            // global out-base per (expert, block)

__device__ __forceinline__ u64 ffma2(u64 a, u64 b, u64 c) {
    u64 d;
    asm("fma.rn.f32x2 %0, %1, %2, %3;" : "=l"(d) : "l"(a), "l"(b), "l"(c));
    return d;
}
__device__ __forceinline__ u64 addx2(u64 a, u64 b) {
    u64 d;
    asm("add.rn.f32x2 %0, %1, %2;" : "=l"(d) : "l"(a), "l"(b));
    return d;
}
__device__ __forceinline__ u64 splat2(float x) {
    u64 r;
    asm("mov.b64 %0, {%1, %1};" : "=l"(r) : "f"(x));
    return r;
}
__device__ __forceinline__ u64 shfl64_xor(u64 v, int m) {
    unsigned lo = (unsigned)v, hi = (unsigned)(v >> 32);
    lo = __shfl_xor_sync(FULLM, lo, m);
    hi = __shfl_xor_sync(FULLM, hi, m);
    return (u64)lo | ((u64)hi << 32);
}
__device__ __forceinline__ float4 ldcs4(const float4* p) {
    float4 v;
    asm("ld.global.cs.v4.f32 {%0,%1,%2,%3}, [%4];"
        : "=f"(v.x), "=f"(v.y), "=f"(v.z), "=f"(v.w) : "l"(p));
    return v;
}
__device__ __forceinline__ ulonglong2 ldg2(const ulonglong2* p) {
    ulonglong2 v;
    asm("ld.global.nc.v2.u64 {%0, %1}, [%2];" : "=l"(v.x), "=l"(v.y) : "l"(p));
    return v;
}

// =====================================================================
// Kernel 0: one-time W swizzle (R14 version)
// =====================================================================
__global__ void wprep_kernel(const float* __restrict__ W) {
    const int idx = blockIdx.x * 256 + threadIdx.x;   // 0..8191 = k*4 + j
    const int k = idx >> 2, j = idx & 3;
    const int i = k >> 7, ln = (k >> 2) & 31, kk = k & 3;
    const int dst = ((i * 4 + kk) * 4 + j) * 32 + ln;
    const float w0 = W[(4 * j + 0) * ND + k];
    const float w1 = W[(4 * j + 1) * ND + k];
    const float w2 = W[(4 * j + 2) * ND + k];
    const float w3 = W[(4 * j + 3) * ND + k];
    ulonglong2 v;
    v.x = (u64)__float_as_uint(w0) | ((u64)__float_as_uint(w1) << 32);
    v.y = (u64)__float_as_uint(w2) | ((u64)__float_as_uint(w3) << 32);
    reinterpret_cast<ulonglong2*>(g_Wt)[dst] = v;
}

// =====================================================================
// Kernel 1: GEMV — 8 tokens/warp + DOUBLE-BUFFERED feature loads.
// =====================================================================
__global__ void __launch_bounds__(256) gemv_kernel(const float* __restrict__ f,
                                                   const float* __restrict__ b) {
    const int lane = threadIdx.x & 31;
    const int wid  = threadIdx.x >> 5;
    const int t0   = (blockIdx.x * 8 + wid) * 8;

    const float4* F = reinterpret_cast<const float4*>(f + (size_t)t0 * ND);
    const ulonglong2* Wt = reinterpret_cast<const ulonglong2*>(g_Wt);

    u64 acc[8][8];
#pragma unroll
    for (int t = 0; t < 8; ++t)
#pragma unroll
        for (int p = 0; p < 8; ++p) acc[t][p] = 0ull;

    float4 a[8];
#pragma unroll
    for (int t = 0; t < 8; ++t) a[t] = ldcs4(F + t * 512 + lane);

    for (int i = 0; i < 16; ++i) {
        float4 nx[8];
        if (i < 15) {
            const int k4 = (i + 1) * 32 + lane;
#pragma unroll
            for (int t = 0; t < 8; ++t) nx[t] = ldcs4(F + t * 512 + k4);
        }
#pragma unroll
        for (int kk = 0; kk < 4; ++kk) {
            const int base = ((i * 4 + kk) * 4) * 32 + lane;
            const ulonglong2 wA = ldg2(Wt + base);
            const ulonglong2 wB = ldg2(Wt + base + 32);
            const ulonglong2 wC = ldg2(Wt + base + 64);
            const ulonglong2 wD = ldg2(Wt + base + 96);
#pragma unroll
            for (int t = 0; t < 8; ++t) {
                const float av = kk == 0 ? a[t].x : kk == 1 ? a[t].y
                               : kk == 2 ? a[t].z : a[t].w;
                const u64 s = splat2(av);
                acc[t][0] = ffma2(s, wA.x, acc[t][0]);
                acc[t][1] = ffma2(s, wA.y, acc[t][1]);
                acc[t][2] = ffma2(s, wB.x, acc[t][2]);
                acc[t][3] = ffma2(s, wB.y, acc[t][3]);
                acc[t][4] = ffma2(s, wC.x, acc[t][4]);
                acc[t][5] = ffma2(s, wC.y, acc[t][5]);
                acc[t][6] = ffma2(s, wD.x, acc[t][6]);
                acc[t][7] = ffma2(s, wD.y, acc[t][7]);
            }
        }
#pragma unroll
        for (int t = 0; t < 8; ++t) a[t] = nx[t];
    }

    u64 keep0 = 0, keep1 = 0;
#pragma unroll
    for (int t = 0; t < 8; ++t) {
#pragma unroll
        for (int p = 0; p < 8; ++p) {
            u64 v = acc[t][p];
#pragma unroll
            for (int o = 16; o; o >>= 1) v = addx2(v, shfl64_xor(v, o));
            if (lane == ((t & 3) * 8 + p)) { if (t < 4) keep0 = v; else keep1 = v; }
        }
    }

    const int p = lane & 7;
    const int g = lane >> 3;
    const float b0 = __ldg(b + 2 * p), b1 = __ldg(b + 2 * p + 1);

#pragma unroll
    for (int pass = 0; pass < 2; ++pass) {
        const int t = t0 + pass * 4 + g;
        const u64 P = pass ? keep1 : keep0;
        const float f0 = __uint_as_float((unsigned)P) + b0;
        const float f1 = __uint_as_float((unsigned)(P >> 32)) + b1;

        float m = fmaxf(f0, f1);
#pragma unroll
        for (int o = 1; o < 8; o <<= 1) m = fmaxf(m, __shfl_xor_sync(FULLM, m, o));
        const float e0 = __expf(f0 - m), e1 = __expf(f1 - m);
        float s = e0 + e1;
#pragma unroll
        for (int o = 1; o < 8; o <<= 1) s += __shfl_xor_sync(FULLM, s, o);
        const float inv = __fdividef(1.f, s);
        g_probsT[(2 * p) * NT + t]     = e0 * inv;
        g_probsT[(2 * p + 1) * NT + t] = e1 * inv;

        unsigned u0 = __float_as_uint(f0), u1 = __float_as_uint(f1);
        u0 = (u0 & 0x80000000u) ? ~u0 : (u0 | 0x80000000u);
        u1 = (u1 & 0x80000000u) ? ~u1 : (u1 | 0x80000000u);
        const u64 k0 = ((u64)u0 << 4) | (u64)(15 - 2 * p);
        const u64 k1 = ((u64)u1 << 4) | (u64)(14 - 2 * p);
        int r0 = (k1 > k0), r1 = (k0 > k1);
#pragma unroll
        for (int j = 1; j < 8; ++j) {
            const u64 o0 = shfl64_xor(k0, j);
            const u64 o1 = shfl64_xor(k1, j);
            r0 += (o0 > k0) + (o1 > k0);
            r1 += (o0 > k1) + (o1 > k1);
        }
        u64 n = ((u64)(2 * p) << (4 * r0)) | ((u64)(2 * p + 1) << (4 * r1));
#pragma unroll
        for (int o = 1; o < 8; o <<= 1) n |= shfl64_xor(n, o);
        if (p == 0) g_prefs[t] = n;
    }
}

// =====================================================================
// Kernel 2: phased balanced assignment (R14 version)
// =====================================================================
#define S_PREF_OFF 0
#define S_CH_OFF   65536
#define S_BLK_OFF  73728                 // [16][32] int
#define S_INT_OFF  (73728 + 2048)
#define SMEM_BYTES (73728 + 2048 + 128)
// s_int: [16] active, [17] start, [18] cut A, [19] cut B

__global__ void __launch_bounds__(1024) assign_kernel() {
    if (blockIdx.x != 0) return;          // grid padded to defeat 1-CTA throttle
    extern __shared__ unsigned char smem[];
    u64*      s_pref = (u64*)(smem + S_PREF_OFF);
    unsigned* s_ch   = (unsigned*)(smem + S_CH_OFF);   // 2048 words
    int*      s_blk  = (int*)(smem + S_BLK_OFF);
    int*      s_int  = (int*)(smem + S_INT_OFF);

    const int tid  = threadIdx.x;
    const int lane = tid & 31;
    const int wid  = tid >> 5;

    for (int i = tid; i < NT; i += 1024) s_pref[i] = g_prefs[i];
    if (tid == 0) { s_int[16] = 0xFFFF; s_int[17] = 0; s_int[18] = CINF; s_int[19] = CINF; }
    __syncthreads();

    // ---- build: warp wid counts+writes its 256-token block ----
    {
        u64 c0 = 0, c1 = 0, c2 = 0, c3 = 0;
#pragma unroll
        for (int i = 0; i < 2; ++i) {
            const int w = wid * 64 + i * 32 + lane;
            unsigned word = 0;
#pragma unroll
            for (int bb = 0; bb < 4; ++bb) {
                const int c = (int)(s_pref[w * 4 + bb] & 15);
                word |= (unsigned)c << (bb * 8);
                const u64 inc = 1ull << ((c & 3) << 4);
                if      ((c >> 2) == 0) c0 += inc;
                else if ((c >> 2) == 1) c1 += inc;
                else if ((c >> 2) == 2) c2 += inc;
                else                    c3 += inc;
            }
            s_ch[w] = word;
        }
#pragma unroll
        for (int o = 16; o; o >>= 1) {
            c0 += __shfl_xor_sync(FULLM, c0, o);
            c1 += __shfl_xor_sync(FULLM, c1, o);
            c2 += __shfl_xor_sync(FULLM, c2, o);
            c3 += __shfl_xor_sync(FULLM, c3, o);
        }
        if (lane < NE) {
            const u64 sel = (lane >> 2) == 0 ? c0 : (lane >> 2) == 1 ? c1
                          : (lane >> 2) == 2 ? c2 : c3;
            s_blk[lane * 32 + wid] = (int)((sel >> ((lane & 3) << 4)) & 0xFFFF);
        }
    }
    __syncthreads();

    // ---------------- phase loop ----------------
    for (int phase = 0; phase < NE; ++phase) {
        const int s = s_int[17];
        const int active  = s_int[16];
        const int cutslot = 18 + (phase & 1);

        if (wid < NE && ((active >> wid) & 1)) {
            const int e = wid;
            const unsigned splat = (unsigned)e * 0x01010101u;
            const int pb   = s >> 8;
            const int ws   = s >> 2;
            const int we_  = (pb + 1) * 64;
            const unsigned mfirst = 0xFFFFFFFFu << ((s & 3) * 8);

            const int i0 = ws + lane * 2;
            unsigned cm0 = 0, cm1 = 0;
            if (i0 < we_) {
                cm0 = __vcmpeq4(s_ch[i0], splat);
                if (i0 == ws) cm0 &= mfirst;
            }
            if (i0 + 1 < we_) cm1 = __vcmpeq4(s_ch[i0 + 1], splat);
            const int lcnt = (__popc(cm0) + __popc(cm1)) >> 3;
            const int ptotal = (int)__reduce_add_sync(FULLM, (unsigned)lcnt);

            const int bfull = s_blk[e * 32 + lane];
            int incl = bfull;
#pragma unroll
            for (int o = 1; o < 32; o <<= 1) {
                const int u = __shfl_up_sync(FULLM, incl, o);
                if (lane >= o) incl += u;
            }
            const int tot     = __shfl_sync(FULLM, incl, 31);
            const int pref_pb = __shfl_sync(FULLM, incl, pb);
            const int need    = CAP - (pref_pb - ptotal);
            const int live    = tot - pref_pb + ptotal;

            if (live >= need) {
                if (ptotal >= need) {
                    int linc = lcnt;
#pragma unroll
                    for (int o = 1; o < 32; o <<= 1) {
                        const int u = __shfl_up_sync(FULLM, linc, o);
                        if (lane >= o) linc += u;
                    }
                    const unsigned bal = __ballot_sync(FULLM, linc >= need);
                    const int cl = __ffs(bal) - 1;
                    if (lane == cl) {
                        int rem = need - (linc - lcnt);
                        int pos = -1;
#pragma unroll
                        for (int bb = 0; bb < 4 && pos < 0; ++bb)
                            if ((cm0 >> (bb * 8)) & 1u && --rem == 0) pos = i0 * 4 + bb;
#pragma unroll
                        for (int bb = 0; bb < 4 && pos < 0; ++bb)
                            if ((cm1 >> (bb * 8)) & 1u && --rem == 0) pos = (i0 + 1) * 4 + bb;
                        atomicMin(&s_int[cutslot], (pos << 4) | e);
                    }
                } else {
                    const int rem2 = need - ptotal;
                    const int minc = incl - pref_pb;
                    const unsigned bal = __ballot_sync(FULLM, lane > pb && minc >= rem2);
                    const int kc   = __ffs(bal) - 1;
                    const int excl = __shfl_sync(FULLM, incl - bfull, kc) - pref_pb;
                    const int rem3 = rem2 - excl;
                    const int j0 = kc * 64 + lane * 2;
                    const unsigned d0 = __vcmpeq4(s_ch[j0], splat);
                    const unsigned d1 = __vcmpeq4(s_ch[j0 + 1], splat);
                    const int lc = (__popc(d0) + __popc(d1)) >> 3;
                    int li = lc;
#pragma unroll
                    for (int o = 1; o < 32; o <<= 1) {
                        const int u = __shfl_up_sync(FULLM, li, o);
                        if (lane >= o) li += u;
                    }
                    const unsigned bal2 = __ballot_sync(FULLM, li >= rem3);
                    const int cl2 = __ffs(bal2) - 1;
                    if (lane == cl2) {
                        int rem = rem3 - (li - lc);
                        int pos = -1;
#pragma unroll
                        for (int bb = 0; bb < 4 && pos < 0; ++bb)
                            if ((d0 >> (bb * 8)) & 1u && --rem == 0) pos = j0 * 4 + bb;
#pragma unroll
                        for (int bb = 0; bb < 4 && pos < 0; ++bb)
                            if ((d1 >> (bb * 8)) & 1u && --rem == 0) pos = (j0 + 1) * 4 + bb;
                        atomicMin(&s_int[cutslot], (pos << 4) | e);
                    }
                }
            }
        }
        __syncthreads();                               // B1: cut final

        const int mv = s_int[cutslot];
        if (mv == CINF) {
            if (tid == 0) s_int[17] = NT;
            __syncthreads();
            continue;
        }
        const int pstar = mv >> 4, es = mv & 15;
        const int nactive = active & ~(1 << es);

        if (tid == 0) {
            s_int[16] = nactive;
            s_int[17] = pstar + 1;
            s_int[cutslot] = CINF;
        }
        {
            const int sn = pstar + 1;
            const int ws = sn >> 2;
            const unsigned splat = (unsigned)es * 0x01010101u;
            const unsigned mfirst = 0xFFFFFFFFu << ((sn & 3) * 8);
            for (int w = ws + tid; w < 2048; w += 1024) {
                unsigned word = s_ch[w];
                unsigned m = __vcmpeq4(word, splat);
                if (w == ws) m &= mfirst;
                if (m) {
                    const int blk = w >> 6;
                    int moved = 0;
                    do {
                        const int bb = (__ffs(m) - 1) >> 3;
                        m &= ~(0xFFu << (bb * 8));
                        u64 pw = s_pref[w * 4 + bb];
                        int c = (int)(pw & 15);
                        while (!((nactive >> c) & 1)) { pw >>= 4; c = (int)(pw & 15); }
                        word = (word & ~(0xFFu << (bb * 8))) | ((unsigned)c << (bb * 8));
                        atomicAdd(&s_blk[c * 32 + blk], 1);
                        ++moved;
                    } while (m);
                    atomicAdd(&s_blk[es * 32 + blk], -moved);
                    s_ch[w] = word;
                }
            }
        }
        __syncthreads();                               // B2: phase done
    }

    // ---- dump choices + per-(expert, block) OUTPUT BASES (prefixed) ----
    for (int i = tid; i < NT / 4; i += 1024) g_ch[i] = s_ch[i];
    if (wid < NE) {
        const int v = s_blk[wid * 32 + lane];
        int incl = v;
#pragma unroll
        for (int o = 1; o < 32; o <<= 1) {
            const int u = __shfl_up_sync(FULLM, incl, o);
            if (lane >= o) incl += u;
        }
        g_bpre[wid * 32 + lane] = wid * CAP + incl - v;   // exclusive prefix
    }
}

// =====================================================================
// Kernel 3: wide epilogue (R14 version)
// =====================================================================
__global__ void __launch_bounds__(256) epilogue_kernel(float* __restrict__ out) {
    __shared__ int s_base[NE];
    __shared__ int s_cnt[8][NE];
    const int b = blockIdx.x, tid = threadIdx.x;
    const int lane = tid & 31, wid = tid >> 5;
    const unsigned ltm = (1u << lane) - 1u;

    if (tid < NE) s_base[tid] = g_bpre[tid * 32 + b];
    if (tid < 8 * NE) s_cnt[tid >> 4][tid & 15] = 0;
    __syncthreads();

    const int t = b * 256 + tid;
    const int e = (int)((g_ch[t >> 2] >> ((t & 3) * 8)) & 0xFFu);
    const unsigned mask = __match_any_sync(FULLM, e);
    const int leader = __ffs(mask) - 1;
    if (lane == leader) s_cnt[wid][e] = __popc(mask);
    __syncthreads();

    if (tid < NE) {
        int acc = 0;
#pragma unroll
        for (int w = 0; w < 8; ++w) {
            const int v = s_cnt[w][tid];
            s_cnt[w][tid] = acc;
            acc += v;
        }
    }
    __syncthreads();

    const int rank = s_base[e] + s_cnt[wid][e] + __popc(mask & ltm);
    out[rank] = (float)t;
    out[NT + t] = g_probsT[e * NT + t];
}

// =====================================================================
extern "C" void kernel_launch(void* const* d_in, const int* in_sizes, int n_in,
                              void* d_out, int out_size) {
    const float* f = (const float*)d_in[0];   // features [8192, 2048] f32
    const float* W = (const float*)d_in[1];   // gate weight [16, 2048] f32
    const float* b = (const float*)d_in[2];   // bias [16] f32
    float* out = (float*)d_out;               // [8192] sort_by_expert ++ [8192] gathered

    wprep_kernel<<<32, 256>>>(W);
    gemv_kernel<<<NT / 64, 256>>>(f, b);

    cudaFuncSetAttribute(assign_kernel,
                         cudaFuncAttributeMaxDynamicSharedMemorySize, SMEM_BYTES);
    assign_kernel<<<148, 1024, SMEM_BYTES>>>();

    epilogue_kernel<<<NT / 256, 256>>>(out);
}